// round 1
// baseline (speedup 1.0000x reference)
#include <cuda_runtime.h>
#include <math.h>

#define BSZ    2
#define SEQ    2048
#define DMODEL 1024
#define NHEAD  16
#define DHEAD  64
#define NTOK   (BSZ * SEQ)   // 4096
#define NPAIR  (DHEAD / 2)   // 32

// Scratch (device globals: allocation-free rule)
__device__ float g_q[(size_t)NTOK * DMODEL];
__device__ float g_k[(size_t)NTOK * DMODEL];
__device__ float g_v[(size_t)NTOK * DMODEL];
__device__ float g_att[(size_t)NTOK * DMODEL];
__device__ float g_cos[SEQ * NPAIR];
__device__ float g_sin[SEQ * NPAIR];

// ---------------------------------------------------------------------------
// RoPE tables: cos/sin(s * theta^{-p/32}) for s in [0,2048), p in [0,32)
// ---------------------------------------------------------------------------
__global__ void rope_table_kernel() {
    int idx = blockIdx.x * blockDim.x + threadIdx.x;
    if (idx >= SEQ * NPAIR) return;
    int s = idx >> 5;
    int p = idx & 31;
    float invf = (float)pow(10000.0, -(double)p / 32.0);
    float ang  = (float)s * invf;
    g_cos[idx] = cosf(ang);
    g_sin[idx] = sinf(ang);
}

// ---------------------------------------------------------------------------
// 128x128x8 fp32 GEMM: C[4096,1024] = A[4096,1024] @ W[1024,1024]
// 256 threads, 8x8 microtile per thread. Optional fused RoPE epilogue.
// ---------------------------------------------------------------------------
template <int ROPE>
__global__ __launch_bounds__(256) void gemm_kernel(const float* __restrict__ A,
                                                   const float* __restrict__ W,
                                                   float* __restrict__ C) {
    __shared__ float As[8][128];   // [k][m]
    __shared__ float Bs[8][128];   // [k][n]

    const int tid = threadIdx.x;
    const int tx  = tid & 15;
    const int ty  = tid >> 4;
    const int bm  = blockIdx.y;
    const int bn  = blockIdx.x;
    const int m0  = ty * 8;
    const int n0  = tx * 8;

    // global load assignments
    const int ar = tid >> 1;           // 0..127 : A row within tile
    const int ak = (tid & 1) * 4;      // 0 or 4 : A k offset
    const int bk = tid >> 5;           // 0..7   : W k row within tile
    const int bc = (tid & 31) * 4;     // 0..124 : W col within tile

    const float* Aptr = A + (size_t)(bm * 128 + ar) * DMODEL + ak;
    const float* Wptr = W + (size_t)bk * DMODEL + bn * 128 + bc;

    float acc[8][8];
#pragma unroll
    for (int i = 0; i < 8; i++)
#pragma unroll
        for (int j = 0; j < 8; j++) acc[i][j] = 0.f;

    float4 av = *(const float4*)(Aptr);
    float4 bv = *(const float4*)(Wptr);

    for (int k0 = 0; k0 < DMODEL; k0 += 8) {
        __syncthreads();
        As[ak + 0][ar] = av.x;
        As[ak + 1][ar] = av.y;
        As[ak + 2][ar] = av.z;
        As[ak + 3][ar] = av.w;
        *(float4*)&Bs[bk][bc] = bv;
        __syncthreads();

        if (k0 + 8 < DMODEL) {   // register prefetch of next tile
            av = *(const float4*)(Aptr + k0 + 8);
            bv = *(const float4*)(Wptr + (size_t)(k0 + 8) * DMODEL);
        }

#pragma unroll
        for (int kk = 0; kk < 8; kk++) {
            float4 a0 = *(const float4*)&As[kk][m0];
            float4 a1 = *(const float4*)&As[kk][m0 + 4];
            float4 b0 = *(const float4*)&Bs[kk][n0];
            float4 b1 = *(const float4*)&Bs[kk][n0 + 4];
            float am[8] = {a0.x, a0.y, a0.z, a0.w, a1.x, a1.y, a1.z, a1.w};
            float bn_[8] = {b0.x, b0.y, b0.z, b0.w, b1.x, b1.y, b1.z, b1.w};
#pragma unroll
            for (int i = 0; i < 8; i++)
#pragma unroll
                for (int j = 0; j < 8; j++) acc[i][j] += am[i] * bn_[j];
        }
    }

    // epilogue
#pragma unroll
    for (int ii = 0; ii < 8; ii++) {
        int row = bm * 128 + m0 + ii;
        float* crow = C + (size_t)row * DMODEL + bn * 128 + n0;
        if (ROPE) {
            int s = row & (SEQ - 1);
            const float* cs = g_cos + s * NPAIR;
            const float* sn = g_sin + s * NPAIR;
#pragma unroll
            for (int jj = 0; jj < 8; jj += 2) {
                int col = bn * 128 + n0 + jj;
                int p   = (col & 63) >> 1;
                float c = cs[p], si = sn[p];
                float a = acc[ii][jj], b = acc[ii][jj + 1];
                acc[ii][jj]     = a * c - b * si;
                acc[ii][jj + 1] = a * si + b * c;
            }
        }
        float4 v0 = make_float4(acc[ii][0], acc[ii][1], acc[ii][2], acc[ii][3]);
        float4 v1 = make_float4(acc[ii][4], acc[ii][5], acc[ii][6], acc[ii][7]);
        *(float4*)(crow)     = v0;
        *(float4*)(crow + 4) = v1;
    }
}

// ---------------------------------------------------------------------------
// fp32 causal flash attention.
// grid (S/64, H, B), 256 threads. 64-row q tile, 64-wide kv tiles.
// smem: Qs[d][i], KPs (K as [d][j], later P as [j][i]), Vs[j][n]. 48KB total.
// ---------------------------------------------------------------------------
__global__ __launch_bounds__(256) void flash_kernel() {
    __shared__ float Qs[64][64];
    __shared__ float KPs[64][64];
    __shared__ float Vs[64][64];

    const int tid = threadIdx.x;
    const int tx  = tid & 15;
    const int ty  = tid >> 4;
    const int qt  = blockIdx.x;
    const int h   = blockIdx.y;
    const int b   = blockIdx.z;
    const int q0  = qt * 64;
    const size_t base = (size_t)b * SEQ * DMODEL + (size_t)h * DHEAD;

    // load Q tile transposed: Qs[d][i]
    {
        const int d0 = (tid & 15) * 4;
#pragma unroll
        for (int it = 0; it < 4; it++) {
            int i = (tid >> 4) + it * 16;
            float4 v = *(const float4*)(g_q + base + (size_t)(q0 + i) * DMODEL + d0);
            Qs[d0 + 0][i] = v.x; Qs[d0 + 1][i] = v.y;
            Qs[d0 + 2][i] = v.z; Qs[d0 + 3][i] = v.w;
        }
    }

    float o[4][4];
    float mi[4], li[4];
#pragma unroll
    for (int i = 0; i < 4; i++) {
        mi[i] = -1e30f; li[i] = 0.f;
#pragma unroll
        for (int j = 0; j < 4; j++) o[i][j] = 0.f;
    }

    const int i0 = ty * 4;     // q rows owned by this thread
    const int n0 = tx * 4;     // kv col (S phase) / out col (PV phase)
    const float scale = 0.125f;    // 1/sqrt(64)

    for (int kt = 0; kt <= qt; kt++) {
        const int kg0 = kt * 64;
        // load K (transposed) and V (natural)
        {
            const int d0 = (tid & 15) * 4;
#pragma unroll
            for (int it = 0; it < 4; it++) {
                int j = (tid >> 4) + it * 16;
                float4 kv = *(const float4*)(g_k + base + (size_t)(kg0 + j) * DMODEL + d0);
                KPs[d0 + 0][j] = kv.x; KPs[d0 + 1][j] = kv.y;
                KPs[d0 + 2][j] = kv.z; KPs[d0 + 3][j] = kv.w;
                float4 vv = *(const float4*)(g_v + base + (size_t)(kg0 + j) * DMODEL + d0);
                *(float4*)&Vs[j][d0] = vv;
            }
        }
        __syncthreads();

        // S = Q K^T (this thread: 4x4 tile)
        float sv[4][4];
#pragma unroll
        for (int i = 0; i < 4; i++)
#pragma unroll
            for (int j = 0; j < 4; j++) sv[i][j] = 0.f;
#pragma unroll 16
        for (int d = 0; d < 64; d++) {
            float4 qv = *(const float4*)&Qs[d][i0];
            float4 kv = *(const float4*)&KPs[d][n0];
            float qa[4] = {qv.x, qv.y, qv.z, qv.w};
            float ka[4] = {kv.x, kv.y, kv.z, kv.w};
#pragma unroll
            for (int i = 0; i < 4; i++)
#pragma unroll
                for (int j = 0; j < 4; j++) sv[i][j] += qa[i] * ka[j];
        }

        // scale + causal mask (only diagonal tile needs the mask)
        if (kt == qt) {
#pragma unroll
            for (int i = 0; i < 4; i++)
#pragma unroll
                for (int j = 0; j < 4; j++)
                    sv[i][j] = (n0 + j > i0 + i) ? -1e30f : sv[i][j] * scale;
        } else {
#pragma unroll
            for (int i = 0; i < 4; i++)
#pragma unroll
                for (int j = 0; j < 4; j++) sv[i][j] *= scale;
        }

        // row max over 64 cols: local max then 16-lane xor reduce
        float rm[4];
#pragma unroll
        for (int i = 0; i < 4; i++) {
            rm[i] = fmaxf(fmaxf(sv[i][0], sv[i][1]), fmaxf(sv[i][2], sv[i][3]));
        }
#pragma unroll
        for (int off = 8; off >= 1; off >>= 1) {
#pragma unroll
            for (int i = 0; i < 4; i++)
                rm[i] = fmaxf(rm[i], __shfl_xor_sync(0xffffffffu, rm[i], off));
        }

        // online softmax update
        float pv[4][4];
        float rs[4];
#pragma unroll
        for (int i = 0; i < 4; i++) {
            float mnew = fmaxf(mi[i], rm[i]);
            float corr = __expf(mi[i] - mnew);
            mi[i] = mnew;
            li[i] *= corr;
#pragma unroll
            for (int n = 0; n < 4; n++) o[i][n] *= corr;
            float acc = 0.f;
#pragma unroll
            for (int j = 0; j < 4; j++) {
                float p = __expf(sv[i][j] - mnew);
                pv[i][j] = p;
                acc += p;
            }
            rs[i] = acc;
        }
#pragma unroll
        for (int off = 8; off >= 1; off >>= 1) {
#pragma unroll
            for (int i = 0; i < 4; i++)
                rs[i] += __shfl_xor_sync(0xffffffffu, rs[i], off);
        }
#pragma unroll
        for (int i = 0; i < 4; i++) li[i] += rs[i];

        __syncthreads();   // everyone done reading KPs as K
        // write P transposed: KPs[j][i]
#pragma unroll
        for (int i = 0; i < 4; i++)
#pragma unroll
            for (int j = 0; j < 4; j++) KPs[n0 + j][i0 + i] = pv[i][j];
        __syncthreads();

        // O += P^T-layout @ V
#pragma unroll 16
        for (int j = 0; j < 64; j++) {
            float4 pr = *(const float4*)&KPs[j][i0];
            float4 vr = *(const float4*)&Vs[j][n0];
            float pa[4] = {pr.x, pr.y, pr.z, pr.w};
            float va[4] = {vr.x, vr.y, vr.z, vr.w};
#pragma unroll
            for (int i = 0; i < 4; i++)
#pragma unroll
                for (int n = 0; n < 4; n++) o[i][n] += pa[i] * va[n];
        }
        __syncthreads();   // before next K/V overwrite
    }

    // write normalized output
#pragma unroll
    for (int i = 0; i < 4; i++) {
        float inv = 1.f / li[i];
        float4 v = make_float4(o[i][0] * inv, o[i][1] * inv, o[i][2] * inv, o[i][3] * inv);
        *(float4*)(g_att + base + (size_t)(q0 + i0 + i) * DMODEL + n0) = v;
    }
}

// ---------------------------------------------------------------------------
extern "C" void kernel_launch(void* const* d_in, const int* in_sizes, int n_in,
                              void* d_out, int out_size) {
    const float* x  = (const float*)d_in[0];
    const float* wq = (const float*)d_in[1];
    const float* wk = (const float*)d_in[2];
    const float* wv = (const float*)d_in[3];
    const float* wo = (const float*)d_in[4];
    float* out = (float*)d_out;

    void *pq, *pk, *pv, *patt;
    cudaGetSymbolAddress(&pq, g_q);
    cudaGetSymbolAddress(&pk, g_k);
    cudaGetSymbolAddress(&pv, g_v);
    cudaGetSymbolAddress(&patt, g_att);

    rope_table_kernel<<<(SEQ * NPAIR + 255) / 256, 256>>>();

    dim3 gg(DMODEL / 128, NTOK / 128);
    gemm_kernel<1><<<gg, 256>>>(x, wq, (float*)pq);
    gemm_kernel<1><<<gg, 256>>>(x, wk, (float*)pk);
    gemm_kernel<0><<<gg, 256>>>(x, wv, (float*)pv);

    dim3 fg(SEQ / 64, NHEAD, BSZ);
    flash_kernel<<<fg, 256>>>();

    gemm_kernel<0><<<gg, 256>>>((const float*)patt, wo, out);
}

// round 9
// speedup vs baseline: 1.3157x; 1.3157x over previous
#include <cuda_runtime.h>
#include <cuda_bf16.h>
#include <math.h>
#include <stdint.h>

#define BSZ    2
#define SEQ    2048
#define DMODEL 1024
#define NHEAD  16
#define DHEAD  64
#define NTOK   (BSZ * SEQ)   // 4096
#define NPAIR  (DHEAD / 2)   // 32

// ---------------- scratch (device globals: allocation-free rule) -----------
__device__ float g_q[(size_t)NTOK * DMODEL];
__device__ float g_k[(size_t)NTOK * DMODEL];
__device__ float g_v[(size_t)NTOK * DMODEL];
__device__ float g_att[(size_t)NTOK * DMODEL];
__device__ float g_cos[SEQ * NPAIR];
__device__ float g_sin[SEQ * NPAIR];

__device__ __nv_bfloat16 g_xh[(size_t)NTOK * DMODEL];
__device__ __nv_bfloat16 g_xl[(size_t)NTOK * DMODEL];
__device__ __nv_bfloat16 g_ah[(size_t)NTOK * DMODEL];
__device__ __nv_bfloat16 g_al[(size_t)NTOK * DMODEL];
__device__ __nv_bfloat16 g_wh[(size_t)4 * DMODEL * DMODEL];  // transposed [N][K]
__device__ __nv_bfloat16 g_wl[(size_t)4 * DMODEL * DMODEL];

// ---------------- baseline-ISA helpers (sm_80+; no arch-specific PTX) ------
__device__ __forceinline__ uint32_t smem_u32(const void* p) {
    uint32_t a;
    asm("{ .reg .u64 t; cvta.to.shared.u64 t, %1; cvt.u32.u64 %0, t; }"
        : "=r"(a) : "l"(p));
    return a;
}
__device__ __forceinline__ void cp16(uint32_t dst, const void* src) {
    asm volatile("cp.async.ca.shared.global [%0], [%1], 16;"
                 :: "r"(dst), "l"(src) : "memory");
}
__device__ __forceinline__ void cp_commit() {
    asm volatile("cp.async.commit_group;" ::: "memory");
}
template <int N>
__device__ __forceinline__ void cp_wait() {
    asm volatile("cp.async.wait_group %0;" :: "n"(N) : "memory");
}
// m16n8k16 row.col bf16 -> f32 accumulate
__device__ __forceinline__ void mma_bf16(float* c, const uint32_t* a, const uint32_t* b) {
    asm volatile("mma.sync.aligned.m16n8k16.row.col.f32.bf16.bf16.f32 "
                 "{%0,%1,%2,%3}, {%4,%5,%6,%7}, {%8,%9}, {%0,%1,%2,%3};"
                 : "+f"(c[0]), "+f"(c[1]), "+f"(c[2]), "+f"(c[3])
                 : "r"(a[0]), "r"(a[1]), "r"(a[2]), "r"(a[3]),
                   "r"(b[0]), "r"(b[1]));
}

// ---------------------------------------------------------------------------
// RoPE tables
// ---------------------------------------------------------------------------
__global__ void rope_table_kernel() {
    int idx = blockIdx.x * blockDim.x + threadIdx.x;
    if (idx >= SEQ * NPAIR) return;
    int s = idx >> 5;
    int p = idx & 31;
    float invf = (float)pow(10000.0, -(double)p / 32.0);
    float ang  = (float)s * invf;
    g_cos[idx] = cosf(ang);
    g_sin[idx] = sinf(ang);
}

// ---------------------------------------------------------------------------
// fp32 -> bf16 hi/lo split (row-major, vectorized)
// ---------------------------------------------------------------------------
__global__ void split_kernel(const float* __restrict__ src,
                             __nv_bfloat16* __restrict__ hi,
                             __nv_bfloat16* __restrict__ lo, int n4) {
    int i = blockIdx.x * blockDim.x + threadIdx.x;
    if (i >= n4) return;
    float4 v = ((const float4*)src)[i];
    float a[4] = {v.x, v.y, v.z, v.w};
    __nv_bfloat16 h[4], l[4];
#pragma unroll
    for (int j = 0; j < 4; j++) {
        h[j] = __float2bfloat16(a[j]);
        l[j] = __float2bfloat16(a[j] - __bfloat162float(h[j]));
    }
    *(__nv_bfloat162*)(hi + 4 * (size_t)i)     = __nv_bfloat162{h[0], h[1]};
    *(__nv_bfloat162*)(hi + 4 * (size_t)i + 2) = __nv_bfloat162{h[2], h[3]};
    *(__nv_bfloat162*)(lo + 4 * (size_t)i)     = __nv_bfloat162{l[0], l[1]};
    *(__nv_bfloat162*)(lo + 4 * (size_t)i + 2) = __nv_bfloat162{l[2], l[3]};
}

// ---------------------------------------------------------------------------
// weight transpose + hi/lo split: w[K][N] fp32 -> wT[N][K] bf16 hi/lo
// ---------------------------------------------------------------------------
__global__ void wsplit_kernel(const float* __restrict__ w,
                              __nv_bfloat16* __restrict__ th,
                              __nv_bfloat16* __restrict__ tl) {
    __shared__ float tile[32][33];
    int tx = threadIdx.x, ty = threadIdx.y;
    int n = blockIdx.x * 32 + tx;
    int k0 = blockIdx.y * 32;
#pragma unroll
    for (int j = 0; j < 32; j += 8)
        tile[ty + j][tx] = w[(size_t)(k0 + ty + j) * DMODEL + n];
    __syncthreads();
    int n0 = blockIdx.x * 32;
#pragma unroll
    for (int j = 0; j < 32; j += 8) {
        float v = tile[tx][ty + j];
        __nv_bfloat16 h = __float2bfloat16(v);
        __nv_bfloat16 l = __float2bfloat16(v - __bfloat162float(h));
        th[(size_t)(n0 + ty + j) * DMODEL + k0 + tx] = h;
        tl[(size_t)(n0 + ty + j) * DMODEL + k0 + tx] = l;
    }
}

// ---------------------------------------------------------------------------
// mma.sync split-bf16 GEMM: C[4096,1024] = A[M,K] @ B^T (B stored [N][K]).
// 128x128 block tile, 8 warps (warp tile 64x32 = 4x4 of m16n8k16).
// K staged 32-wide, cp.async double buffered. 3 MMAs/k-tile: AhBh+AhBl+AlBh.
// ---------------------------------------------------------------------------
#define KT      32
#define NSTAGE  (DMODEL / KT)     // 32
#define ROWP    40                // padded row length (bf16) -> conflict-free LDS
#define TILE_E  (128 * ROWP)      // elements per tile (one of Ah/Al/Bh/Bl)
#define BUF_E   (4 * TILE_E)      // elements per stage buffer
#define SMEM_DYN (2 * BUF_E * 2)  // bytes: 2 buffers * 4 tiles * 5120 elem * 2B = 81920

template <int ROPE>
__global__ __launch_bounds__(256)
void gemm_mma(const __nv_bfloat16* __restrict__ Ah,
              const __nv_bfloat16* __restrict__ Al,
              const __nv_bfloat16* __restrict__ Bh,
              const __nv_bfloat16* __restrict__ Bl,
              float* __restrict__ C) {
    extern __shared__ __nv_bfloat16 sm[];
    const uint32_t sb_u32 = smem_u32(sm);

    const int tid = threadIdx.x;
    const int bm = blockIdx.y, bn = blockIdx.x;
    const int wid = tid >> 5, lane = tid & 31;
    const int wm = wid & 1;        // 0..1  (64-row half)
    const int wn = wid >> 1;       // 0..3  (32-col quarter)
    const int g = lane >> 2;       // 0..7
    const int t = lane & 3;        // 0..3

    const __nv_bfloat16* gAh = Ah + (size_t)bm * 128 * DMODEL;
    const __nv_bfloat16* gAl = Al + (size_t)bm * 128 * DMODEL;
    const __nv_bfloat16* gBh = Bh + (size_t)bn * 128 * DMODEL;
    const __nv_bfloat16* gBl = Bl + (size_t)bn * 128 * DMODEL;

    // issue cp.async for one stage into buffer `buf`
    auto load_stage = [&](int stage, int buf) {
        const int k0 = stage * KT;
        const uint32_t base = sb_u32 + (uint32_t)buf * (BUF_E * 2);
#pragma unroll
        for (int i = 0; i < 8; i++) {
            const int tile = i >> 1;                  // 0=Ah 1=Al 2=Bh 3=Bl
            const int cc = (i & 1) * 256 + tid;       // 0..511
            const int row = cc >> 2, seg = cc & 3;    // row 0..127, 16B seg 0..3
            const __nv_bfloat16* gsrc =
                (tile == 0 ? gAh : tile == 1 ? gAl : tile == 2 ? gBh : gBl)
                + (size_t)row * DMODEL + k0 + seg * 8;
            const uint32_t dst = base + (uint32_t)(tile * TILE_E + row * ROWP + seg * 8) * 2;
            cp16(dst, gsrc);
        }
        cp_commit();
    };

    float acc[4][4][4];
#pragma unroll
    for (int mt = 0; mt < 4; mt++)
#pragma unroll
        for (int nt = 0; nt < 4; nt++)
#pragma unroll
            for (int e = 0; e < 4; e++) acc[mt][nt][e] = 0.f;

    load_stage(0, 0);

    for (int s = 0; s < NSTAGE; s++) {
        const int buf = s & 1;
        if (s + 1 < NSTAGE) {
            load_stage(s + 1, 1 - buf);
            cp_wait<1>();
        } else {
            cp_wait<0>();
        }
        __syncthreads();

        const __nv_bfloat16* sAh = sm + buf * BUF_E;
        const __nv_bfloat16* sAl = sAh + TILE_E;
        const __nv_bfloat16* sBh = sAl + TILE_E;
        const __nv_bfloat16* sBl = sBh + TILE_E;

#pragma unroll
        for (int ks = 0; ks < 2; ks++) {
            const int kb = ks * 16 + t * 2;
            uint32_t ah[4][4], al[4][4], bh[4][2], bl[4][2];
#pragma unroll
            for (int mt = 0; mt < 4; mt++) {
                const int r = wm * 64 + mt * 16 + g;
                ah[mt][0] = *(const uint32_t*)(sAh + r * ROWP + kb);
                ah[mt][1] = *(const uint32_t*)(sAh + (r + 8) * ROWP + kb);
                ah[mt][2] = *(const uint32_t*)(sAh + r * ROWP + kb + 8);
                ah[mt][3] = *(const uint32_t*)(sAh + (r + 8) * ROWP + kb + 8);
                al[mt][0] = *(const uint32_t*)(sAl + r * ROWP + kb);
                al[mt][1] = *(const uint32_t*)(sAl + (r + 8) * ROWP + kb);
                al[mt][2] = *(const uint32_t*)(sAl + r * ROWP + kb + 8);
                al[mt][3] = *(const uint32_t*)(sAl + (r + 8) * ROWP + kb + 8);
            }
#pragma unroll
            for (int nt = 0; nt < 4; nt++) {
                const int n = wn * 32 + nt * 8 + g;
                bh[nt][0] = *(const uint32_t*)(sBh + n * ROWP + kb);
                bh[nt][1] = *(const uint32_t*)(sBh + n * ROWP + kb + 8);
                bl[nt][0] = *(const uint32_t*)(sBl + n * ROWP + kb);
                bl[nt][1] = *(const uint32_t*)(sBl + n * ROWP + kb + 8);
            }
#pragma unroll
            for (int mt = 0; mt < 4; mt++)
#pragma unroll
                for (int nt = 0; nt < 4; nt++) {
                    mma_bf16(acc[mt][nt], ah[mt], bh[nt]);
                    mma_bf16(acc[mt][nt], ah[mt], bl[nt]);
                    mma_bf16(acc[mt][nt], al[mt], bh[nt]);
                }
        }
        __syncthreads();
    }

    // epilogue: optional RoPE, fp32 stores (pairs are (even,odd) head dims)
#pragma unroll
    for (int mt = 0; mt < 4; mt++) {
        const int r0 = bm * 128 + wm * 64 + mt * 16 + g;
        const int r1 = r0 + 8;
#pragma unroll
        for (int nt = 0; nt < 4; nt++) {
            const int cgl = bn * 128 + wn * 32 + nt * 8 + t * 2;
            float* a = acc[mt][nt];
            if (ROPE) {
                const int pi = (cgl & 63) >> 1;
                const int s0 = r0 & (SEQ - 1);
                const int s1 = r1 & (SEQ - 1);
                float c0 = g_cos[s0 * NPAIR + pi], si0 = g_sin[s0 * NPAIR + pi];
                float c1 = g_cos[s1 * NPAIR + pi], si1 = g_sin[s1 * NPAIR + pi];
                float x0 = a[0], y0 = a[1], x1 = a[2], y1 = a[3];
                a[0] = x0 * c0 - y0 * si0; a[1] = x0 * si0 + y0 * c0;
                a[2] = x1 * c1 - y1 * si1; a[3] = x1 * si1 + y1 * c1;
            }
            *(float2*)(C + (size_t)r0 * DMODEL + cgl) = make_float2(a[0], a[1]);
            *(float2*)(C + (size_t)r1 * DMODEL + cgl) = make_float2(a[2], a[3]);
        }
    }
}

// ---------------------------------------------------------------------------
// fp32 causal flash attention (unchanged from Round 1 — verified on HW)
// ---------------------------------------------------------------------------
__global__ __launch_bounds__(256) void flash_kernel() {
    __shared__ float Qs[64][64];
    __shared__ float KPs[64][64];
    __shared__ float Vs[64][64];

    const int tid = threadIdx.x;
    const int tx  = tid & 15;
    const int ty  = tid >> 4;
    const int qt  = blockIdx.x;
    const int h   = blockIdx.y;
    const int b   = blockIdx.z;
    const int q0  = qt * 64;
    const size_t base = (size_t)b * SEQ * DMODEL + (size_t)h * DHEAD;

    {
        const int d0 = (tid & 15) * 4;
#pragma unroll
        for (int it = 0; it < 4; it++) {
            int i = (tid >> 4) + it * 16;
            float4 v = *(const float4*)(g_q + base + (size_t)(q0 + i) * DMODEL + d0);
            Qs[d0 + 0][i] = v.x; Qs[d0 + 1][i] = v.y;
            Qs[d0 + 2][i] = v.z; Qs[d0 + 3][i] = v.w;
        }
    }

    float o[4][4];
    float mi[4], li[4];
#pragma unroll
    for (int i = 0; i < 4; i++) {
        mi[i] = -1e30f; li[i] = 0.f;
#pragma unroll
        for (int j = 0; j < 4; j++) o[i][j] = 0.f;
    }

    const int i0 = ty * 4;
    const int n0 = tx * 4;
    const float scale = 0.125f;

    for (int kt = 0; kt <= qt; kt++) {
        const int kg0 = kt * 64;
        {
            const int d0 = (tid & 15) * 4;
#pragma unroll
            for (int it = 0; it < 4; it++) {
                int j = (tid >> 4) + it * 16;
                float4 kv = *(const float4*)(g_k + base + (size_t)(kg0 + j) * DMODEL + d0);
                KPs[d0 + 0][j] = kv.x; KPs[d0 + 1][j] = kv.y;
                KPs[d0 + 2][j] = kv.z; KPs[d0 + 3][j] = kv.w;
                float4 vv = *(const float4*)(g_v + base + (size_t)(kg0 + j) * DMODEL + d0);
                *(float4*)&Vs[j][d0] = vv;
            }
        }
        __syncthreads();

        float sv[4][4];
#pragma unroll
        for (int i = 0; i < 4; i++)
#pragma unroll
            for (int j = 0; j < 4; j++) sv[i][j] = 0.f;
#pragma unroll 16
        for (int d = 0; d < 64; d++) {
            float4 qv = *(const float4*)&Qs[d][i0];
            float4 kv = *(const float4*)&KPs[d][n0];
            float qa[4] = {qv.x, qv.y, qv.z, qv.w};
            float ka[4] = {kv.x, kv.y, kv.z, kv.w};
#pragma unroll
            for (int i = 0; i < 4; i++)
#pragma unroll
                for (int j = 0; j < 4; j++) sv[i][j] += qa[i] * ka[j];
        }

        if (kt == qt) {
#pragma unroll
            for (int i = 0; i < 4; i++)
#pragma unroll
                for (int j = 0; j < 4; j++)
                    sv[i][j] = (n0 + j > i0 + i) ? -1e30f : sv[i][j] * scale;
        } else {
#pragma unroll
            for (int i = 0; i < 4; i++)
#pragma unroll
                for (int j = 0; j < 4; j++) sv[i][j] *= scale;
        }

        float rm[4];
#pragma unroll
        for (int i = 0; i < 4; i++)
            rm[i] = fmaxf(fmaxf(sv[i][0], sv[i][1]), fmaxf(sv[i][2], sv[i][3]));
#pragma unroll
        for (int off = 8; off >= 1; off >>= 1) {
#pragma unroll
            for (int i = 0; i < 4; i++)
                rm[i] = fmaxf(rm[i], __shfl_xor_sync(0xffffffffu, rm[i], off));
        }

        float pv[4][4];
        float rs[4];
#pragma unroll
        for (int i = 0; i < 4; i++) {
            float mnew = fmaxf(mi[i], rm[i]);
            float corr = __expf(mi[i] - mnew);
            mi[i] = mnew;
            li[i] *= corr;
#pragma unroll
            for (int n = 0; n < 4; n++) o[i][n] *= corr;
            float acc2 = 0.f;
#pragma unroll
            for (int j = 0; j < 4; j++) {
                float p = __expf(sv[i][j] - mnew);
                pv[i][j] = p;
                acc2 += p;
            }
            rs[i] = acc2;
        }
#pragma unroll
        for (int off = 8; off >= 1; off >>= 1) {
#pragma unroll
            for (int i = 0; i < 4; i++)
                rs[i] += __shfl_xor_sync(0xffffffffu, rs[i], off);
        }
#pragma unroll
        for (int i = 0; i < 4; i++) li[i] += rs[i];

        __syncthreads();
#pragma unroll
        for (int i = 0; i < 4; i++)
#pragma unroll
            for (int j = 0; j < 4; j++) KPs[n0 + j][i0 + i] = pv[i][j];
        __syncthreads();

#pragma unroll 16
        for (int j = 0; j < 64; j++) {
            float4 pr = *(const float4*)&KPs[j][i0];
            float4 vr = *(const float4*)&Vs[j][n0];
            float pa[4] = {pr.x, pr.y, pr.z, pr.w};
            float va[4] = {vr.x, vr.y, vr.z, vr.w};
#pragma unroll
            for (int i = 0; i < 4; i++)
#pragma unroll
                for (int n = 0; n < 4; n++) o[i][n] += pa[i] * va[n];
        }
        __syncthreads();
    }

#pragma unroll
    for (int i = 0; i < 4; i++) {
        float inv = 1.f / li[i];
        float4 v = make_float4(o[i][0] * inv, o[i][1] * inv, o[i][2] * inv, o[i][3] * inv);
        *(float4*)(g_att + base + (size_t)(q0 + i0 + i) * DMODEL + n0) = v;
    }
}

// ---------------------------------------------------------------------------
extern "C" void kernel_launch(void* const* d_in, const int* in_sizes, int n_in,
                              void* d_out, int out_size) {
    const float* x  = (const float*)d_in[0];
    const float* wq = (const float*)d_in[1];
    const float* wk = (const float*)d_in[2];
    const float* wv = (const float*)d_in[3];
    const float* wo = (const float*)d_in[4];
    float* out = (float*)d_out;

    void *pq, *pk, *pv, *patt, *pxh, *pxl, *pah, *pal, *pwh, *pwl;
    cudaGetSymbolAddress(&pq, g_q);
    cudaGetSymbolAddress(&pk, g_k);
    cudaGetSymbolAddress(&pv, g_v);
    cudaGetSymbolAddress(&patt, g_att);
    cudaGetSymbolAddress(&pxh, g_xh);
    cudaGetSymbolAddress(&pxl, g_xl);
    cudaGetSymbolAddress(&pah, g_ah);
    cudaGetSymbolAddress(&pal, g_al);
    cudaGetSymbolAddress(&pwh, g_wh);
    cudaGetSymbolAddress(&pwl, g_wl);

    __nv_bfloat16* xh = (__nv_bfloat16*)pxh;
    __nv_bfloat16* xl = (__nv_bfloat16*)pxl;
    __nv_bfloat16* ah = (__nv_bfloat16*)pah;
    __nv_bfloat16* al = (__nv_bfloat16*)pal;
    __nv_bfloat16* wh = (__nv_bfloat16*)pwh;
    __nv_bfloat16* wl = (__nv_bfloat16*)pwl;
    const size_t WSZ = (size_t)DMODEL * DMODEL;

    cudaFuncSetAttribute(gemm_mma<0>, cudaFuncAttributeMaxDynamicSharedMemorySize, SMEM_DYN);
    cudaFuncSetAttribute(gemm_mma<1>, cudaFuncAttributeMaxDynamicSharedMemorySize, SMEM_DYN);

    rope_table_kernel<<<(SEQ * NPAIR + 255) / 256, 256>>>();

    int n4 = NTOK * DMODEL / 4;
    split_kernel<<<(n4 + 255) / 256, 256>>>(x, xh, xl, n4);

    dim3 wt(32, 8);
    dim3 wg(DMODEL / 32, DMODEL / 32);
    wsplit_kernel<<<wg, wt>>>(wq, wh + 0 * WSZ, wl + 0 * WSZ);
    wsplit_kernel<<<wg, wt>>>(wk, wh + 1 * WSZ, wl + 1 * WSZ);
    wsplit_kernel<<<wg, wt>>>(wv, wh + 2 * WSZ, wl + 2 * WSZ);
    wsplit_kernel<<<wg, wt>>>(wo, wh + 3 * WSZ, wl + 3 * WSZ);

    dim3 gg(DMODEL / 128, NTOK / 128);   // (8, 32)
    gemm_mma<1><<<gg, 256, SMEM_DYN>>>(xh, xl, wh + 0 * WSZ, wl + 0 * WSZ, (float*)pq);
    gemm_mma<1><<<gg, 256, SMEM_DYN>>>(xh, xl, wh + 1 * WSZ, wl + 1 * WSZ, (float*)pk);
    gemm_mma<0><<<gg, 256, SMEM_DYN>>>(xh, xl, wh + 2 * WSZ, wl + 2 * WSZ, (float*)pv);

    dim3 fg(SEQ / 64, NHEAD, BSZ);
    flash_kernel<<<fg, 256>>>();

    split_kernel<<<(n4 + 255) / 256, 256>>>((const float*)patt, ah, al, n4);
    gemm_mma<0><<<gg, 256, SMEM_DYN>>>(ah, al, wh + 3 * WSZ, wl + 3 * WSZ, out);
}